// round 9
// baseline (speedup 1.0000x reference)
#include <cuda_runtime.h>
#include <cuda_fp16.h>
#include <cuda_bf16.h>
#include <cstdint>

#define NJ 17
#define DM 128
#define NEDGE 49
#define NROWS 66096          // 3888 * 17
#define NFR 3888
#define MTILES 517           // ceil(66096/128)
#define NCHUNK 10            // 640 / 64
#define KSTRIDE 136          // smem row stride (bf16 elems), conflict-free ldmatrix

// ---------------- device scratch ----------------
__device__ float g_X0[(size_t)NROWS * DM];
__device__ float g_skip[NROWS];
__device__ __align__(16) __nv_bfloat16 g_ah[(size_t)MTILES * 128 * 128];
__device__ __align__(16) __nv_bfloat16 g_al[(size_t)MTILES * 128 * 128];
__device__ __align__(16) __nv_bfloat16 g_bh[640 * 128];
__device__ __align__(16) __nv_bfloat16 g_bl[640 * 128];
__device__ float g_bias[640];
__device__ float g_lgaw[DM];         // lg[k]*aw[k]
__device__ float g_c1;               // sum lg*aw
__device__ float g_c2;               // sum lb*aw + ab
__device__ __align__(16) __half g_lr[(size_t)NROWS * 512];
__device__ __align__(16) float g_v[(size_t)NROWS * DM];

// ---------------- adjacency ----------------
__device__ __constant__ int c_row_start[18] =
    {0,4,7,10,12,15,18,20,23,28,31,33,36,39,41,44,47,49};
__device__ __constant__ signed char c_nbr[NEDGE] = {
    0,1,4,7,  0,1,2,  1,2,3,  2,3,  0,4,5,  4,5,6,  5,6,  0,7,8,
    7,8,9,11,14,  8,9,10,  9,10,  8,11,12,  11,12,13,  12,13,
    8,14,15,  14,15,16,  15,16};
__device__ __constant__ signed char c_erow[NEDGE] = {
    0,0,0,0,  1,1,1,  2,2,2,  3,3,  4,4,4,  5,5,5,  6,6,  7,7,7,
    8,8,8,8,8,  9,9,9,  10,10,  11,11,11,  12,12,12,  13,13,
    14,14,14,  15,15,15,  16,16};

// ---------------- helpers ----------------
__device__ __forceinline__ uint32_t smem_u32(const void* p) {
    uint32_t a;
    asm("{ .reg .u64 t; cvta.to.shared.u64 t, %1; cvt.u32.u64 %0, t; }" : "=r"(a) : "l"(p));
    return a;
}
__device__ __forceinline__ void ldm4(uint32_t* r, uint32_t addr) {
    asm volatile("ldmatrix.sync.aligned.m8n8.x4.shared.b16 {%0,%1,%2,%3}, [%4];"
                 : "=r"(r[0]), "=r"(r[1]), "=r"(r[2]), "=r"(r[3]) : "r"(addr));
}
__device__ __forceinline__ void mma_bf16(float* c, const uint32_t* a, const uint32_t* b) {
    asm volatile("mma.sync.aligned.m16n8k16.row.col.f32.bf16.bf16.f32 "
                 "{%0,%1,%2,%3}, {%4,%5,%6,%7}, {%8,%9}, {%0,%1,%2,%3};"
                 : "+f"(c[0]), "+f"(c[1]), "+f"(c[2]), "+f"(c[3])
                 : "r"(a[0]), "r"(a[1]), "r"(a[2]), "r"(a[3]), "r"(b[0]), "r"(b[1]));
}

// LN + skip + bf16 hi/lo split for one row held by one warp.
// Single interleaved 3-way warp reduction: s=Σx, q=Σx², t=Σ x·(lg·aw).
__device__ __forceinline__ void ln_split_row(
    float v0, float v1, float v2, float v3, int lane, size_t grow,
    const float* __restrict__ lg, const float* __restrict__ lb)
{
    int k = lane * 4;
    float s = v0 + v1 + v2 + v3;
    float q = v0 * v0 + v1 * v1 + v2 * v2 + v3 * v3;
    float t = v0 * g_lgaw[k] + v1 * g_lgaw[k + 1]
            + v2 * g_lgaw[k + 2] + v3 * g_lgaw[k + 3];
#pragma unroll
    for (int o = 16; o; o >>= 1) {
        s += __shfl_xor_sync(0xffffffffu, s, o);
        q += __shfl_xor_sync(0xffffffffu, q, o);
        t += __shfl_xor_sync(0xffffffffu, t, o);
    }
    float m = s * (1.0f / 128.0f);
    float var = q * (1.0f / 128.0f) - m * m;
    float rstd = rsqrtf(var + 1e-5f);
    if (lane == 0) {
        float ad = rstd * (t - m * g_c1) + g_c2;
        g_skip[grow] = 1.0f / (1.0f + __expf(-ad));
    }
    float n0 = (v0 - m) * rstd * __ldg(lg + k)     + __ldg(lb + k);
    float n1 = (v1 - m) * rstd * __ldg(lg + k + 1) + __ldg(lb + k + 1);
    float n2 = (v2 - m) * rstd * __ldg(lg + k + 2) + __ldg(lb + k + 2);
    float n3 = (v3 - m) * rstd * __ldg(lg + k + 3) + __ldg(lb + k + 3);

    __nv_bfloat16 h0 = __float2bfloat16(n0), h1 = __float2bfloat16(n1);
    __nv_bfloat16 h2 = __float2bfloat16(n2), h3 = __float2bfloat16(n3);
    __nv_bfloat162 ph01 = __halves2bfloat162(h0, h1);
    __nv_bfloat162 ph23 = __halves2bfloat162(h2, h3);
    __nv_bfloat162 pl01 = __halves2bfloat162(
        __float2bfloat16(n0 - __bfloat162float(h0)),
        __float2bfloat16(n1 - __bfloat162float(h1)));
    __nv_bfloat162 pl23 = __halves2bfloat162(
        __float2bfloat16(n2 - __bfloat162float(h2)),
        __float2bfloat16(n3 - __bfloat162float(h3)));
    uint2 uh, ul;
    uh.x = *reinterpret_cast<uint32_t*>(&ph01);
    uh.y = *reinterpret_cast<uint32_t*>(&ph23);
    ul.x = *reinterpret_cast<uint32_t*>(&pl01);
    ul.y = *reinterpret_cast<uint32_t*>(&pl23);
    *reinterpret_cast<uint2*>(g_ah + grow * 128 + k) = uh;
    *reinterpret_cast<uint2*>(g_al + grow * 128 + k) = ul;
}

// ---------------- prologue: weight split + skip-gate constants ----------------
__global__ void prep_kernel(const float* __restrict__ w1, const float* __restrict__ b1,
                            const float* __restrict__ w2, const float* __restrict__ b2,
                            const float* __restrict__ vw, const float* __restrict__ vb,
                            const float* __restrict__ lg, const float* __restrict__ lb,
                            const float* __restrict__ aw, const float* __restrict__ ab)
{
    int idx = blockIdx.x * blockDim.x + threadIdx.x;
    if (idx < 640 * 128) {
        int n = idx >> 7;
        int k = idx & 127;
        float w = (n < 256) ? w1[k * 256 + n]
                : (n < 512) ? w2[k * 256 + (n - 256)]
                            : vw[k * 128 + (n - 512)];
        __nv_bfloat16 h = __float2bfloat16(w);
        __nv_bfloat16 l = __float2bfloat16(w - __bfloat162float(h));
        g_bh[idx] = h;
        g_bl[idx] = l;
    }
    if (idx < 640) {
        g_bias[idx] = (idx < 256) ? b1[idx]
                    : (idx < 512) ? b2[idx - 256]
                                  : vb[idx - 512];
    }
    if (idx < DM) g_lgaw[idx] = lg[idx] * aw[idx];
    if (idx == 0) {
        float c1 = 0.f, c2 = 0.f;
        for (int k = 0; k < DM; k++) { c1 += lg[k] * aw[k]; c2 += lb[k] * aw[k]; }
        g_c1 = c1;
        g_c2 = c2 + ab[0];
    }
}

// ---------------- outer LN + first inner LN/split: x -> g_X0, g_ah/al, g_skip ----------------
__global__ __launch_bounds__(256) void outer_fused_kernel(
    const float* __restrict__ x,
    const float* __restrict__ og, const float* __restrict__ ob,
    const float* __restrict__ lg, const float* __restrict__ lb)
{
    size_t row = (size_t)blockIdx.x * 8 + (threadIdx.x >> 5);
    int lane = threadIdx.x & 31;
    float4 v = *reinterpret_cast<const float4*>(x + row * DM + lane * 4);
    float s = v.x + v.y + v.z + v.w;
    float q = v.x * v.x + v.y * v.y + v.z * v.z + v.w * v.w;
#pragma unroll
    for (int o = 16; o; o >>= 1) {
        s += __shfl_xor_sync(0xffffffffu, s, o);
        q += __shfl_xor_sync(0xffffffffu, q, o);
    }
    float m = s * (1.0f / 128.0f);
    float rstd = rsqrtf(q * (1.0f / 128.0f) - m * m + 1e-5f);
    int k = lane * 4;
    float4 o;
    o.x = (v.x - m) * rstd * __ldg(og + k)     + __ldg(ob + k);
    o.y = (v.y - m) * rstd * __ldg(og + k + 1) + __ldg(ob + k + 1);
    o.z = (v.z - m) * rstd * __ldg(og + k + 2) + __ldg(ob + k + 2);
    o.w = (v.w - m) * rstd * __ldg(og + k + 3) + __ldg(ob + k + 3);
    *reinterpret_cast<float4*>(g_X0 + row * DM + k) = o;
    ln_split_row(o.x, o.y, o.z, o.w, lane, row, lg, lb);
}

// ---------------- GEMM: 128M x 64N tile, K=128 one-shot, 3-term bf16 split ----------------
#define TILE_A (128 * KSTRIDE)
#define TILE_B (64 * KSTRIDE)
#define GEMM_SMEM ((2 * TILE_A + 2 * TILE_B) * 2)   // 104448 bytes -> 2 CTAs/SM

__global__ __launch_bounds__(256) void gemm_kernel()
{
    extern __shared__ __nv_bfloat16 sm[];
    __nv_bfloat16* sAh = sm;
    __nv_bfloat16* sAl = sm + TILE_A;
    __nv_bfloat16* sBh = sm + 2 * TILE_A;
    __nv_bfloat16* sBl = sm + 2 * TILE_A + TILE_B;

    const int tid = threadIdx.x;
    const int mtile = blockIdx.x;
    const int chunk = blockIdx.y;

    {
        const uint4* gAh = reinterpret_cast<const uint4*>(g_ah + (size_t)mtile * 128 * 128);
        const uint4* gAl = reinterpret_cast<const uint4*>(g_al + (size_t)mtile * 128 * 128);
        for (int i = tid; i < 2048; i += 256) {
            int row = i >> 4, c = i & 15;
            int d = row * KSTRIDE + c * 8;
            *reinterpret_cast<uint4*>(sAh + d) = gAh[i];
            *reinterpret_cast<uint4*>(sAl + d) = gAl[i];
        }
        const uint4* gBh = reinterpret_cast<const uint4*>(g_bh + (size_t)chunk * 64 * 128);
        const uint4* gBl = reinterpret_cast<const uint4*>(g_bl + (size_t)chunk * 64 * 128);
        for (int i = tid; i < 1024; i += 256) {
            int row = i >> 4, c = i & 15;
            int d = row * KSTRIDE + c * 8;
            *reinterpret_cast<uint4*>(sBh + d) = gBh[i];
            *reinterpret_cast<uint4*>(sBl + d) = gBl[i];
        }
    }
    __syncthreads();

    const int wid = tid >> 5, lane = tid & 31;
    const int wm = wid >> 1, wn = wid & 1;
    const int mBase = wm * 32, nBase = wn * 32;
    const int g = lane >> 3, r = lane & 7;

    const int a_row = r + (g & 1) * 8, a_k = (g >> 1) * 8;
    const int b_n = r + (g >> 1) * 8, b_k = (g & 1) * 8;
    uint32_t aBaseH = smem_u32(sAh) + ((mBase + a_row) * KSTRIDE + a_k) * 2;
    uint32_t aBaseL = smem_u32(sAl) + ((mBase + a_row) * KSTRIDE + a_k) * 2;
    uint32_t bBaseH = smem_u32(sBh) + ((nBase + b_n) * KSTRIDE + b_k) * 2;
    uint32_t bBaseL = smem_u32(sBl) + ((nBase + b_n) * KSTRIDE + b_k) * 2;

    float acc[2][4][4];
#pragma unroll
    for (int mt = 0; mt < 2; mt++)
#pragma unroll
        for (int nt = 0; nt < 4; nt++)
#pragma unroll
            for (int q = 0; q < 4; q++) acc[mt][nt][q] = 0.f;

#pragma unroll 2
    for (int k0 = 0; k0 < 128; k0 += 16) {
        uint32_t ah[2][4], al[2][4], bh[4][2], bl[4][2];
#pragma unroll
        for (int mt = 0; mt < 2; mt++) {
            uint32_t off = (uint32_t)(mt * 16 * KSTRIDE + k0) * 2;
            ldm4(ah[mt], aBaseH + off);
            ldm4(al[mt], aBaseL + off);
        }
#pragma unroll
        for (int p = 0; p < 2; p++) {
            uint32_t off = (uint32_t)(p * 16 * KSTRIDE + k0) * 2;
            uint32_t t[4];
            ldm4(t, bBaseH + off);
            bh[2 * p][0] = t[0]; bh[2 * p][1] = t[1];
            bh[2 * p + 1][0] = t[2]; bh[2 * p + 1][1] = t[3];
            ldm4(t, bBaseL + off);
            bl[2 * p][0] = t[0]; bl[2 * p][1] = t[1];
            bl[2 * p + 1][0] = t[2]; bl[2 * p + 1][1] = t[3];
        }
#pragma unroll
        for (int mt = 0; mt < 2; mt++)
#pragma unroll
            for (int nt = 0; nt < 4; nt++) {
                mma_bf16(acc[mt][nt], ah[mt], bh[nt]);
                mma_bf16(acc[mt][nt], al[mt], bh[nt]);
                mma_bf16(acc[mt][nt], ah[mt], bl[nt]);
            }
    }

    const int qrow = lane >> 2, qcol = (lane & 3) * 2;
#pragma unroll
    for (int mt = 0; mt < 2; mt++) {
#pragma unroll
        for (int nt = 0; nt < 4; nt++) {
            int row0 = mtile * 128 + mBase + mt * 16 + qrow;
            int col = nBase + nt * 8 + qcol;
            int gcol = chunk * 64 + col;
            float b0 = g_bias[gcol], b1 = g_bias[gcol + 1];
            float c0 = acc[mt][nt][0] + b0, c1 = acc[mt][nt][1] + b1;
            float c2 = acc[mt][nt][2] + b0, c3 = acc[mt][nt][3] + b1;
            if (chunk < 8) {
                if (row0 < NROWS)
                    *reinterpret_cast<__half2*>(&g_lr[(size_t)row0 * 512 + gcol]) =
                        __halves2half2(__float2half(c0), __float2half(c1));
                if (row0 + 8 < NROWS)
                    *reinterpret_cast<__half2*>(&g_lr[(size_t)(row0 + 8) * 512 + gcol]) =
                        __halves2half2(__float2half(c2), __float2half(c3));
            } else {
                int vc = gcol - 512;
                if (row0 < NROWS) {
                    float2 o; o.x = c0; o.y = c1;
                    *reinterpret_cast<float2*>(&g_v[(size_t)row0 * DM + vc]) = o;
                }
                if (row0 + 8 < NROWS) {
                    float2 o; o.x = c2; o.y = c3;
                    *reinterpret_cast<float2*>(&g_v[(size_t)(row0 + 8) * DM + vc]) = o;
                }
            }
        }
    }
}

// ---------------- attention (2 frames / 256-thread CTA) + fused next-iter LN ----------------
// dyn smem layout (bytes):
#define AT_LR    0                       // 2*17*512 half  = 34816
#define AT_V     34816                   // 2*17*128 float = 17408
#define AT_XNEW  52224                   // 2*17*128 float = 17408
#define AT_SC    69632                   // 196 float      = 784
#define AT_SK    70416                   // 34 float       = 136
#define AT_PSW   70560                   // 128 float      = 512
#define ATTN_SMEM 71072

__global__ __launch_bounds__(256) void attn_fused_kernel(
    const float* __restrict__ psw,
    const float* __restrict__ lg, const float* __restrict__ lb,
    float* __restrict__ out, int last)
{
    extern __shared__ char asm_[];
    __half* LR   = reinterpret_cast<__half*>(asm_ + AT_LR);
    float*  V    = reinterpret_cast<float*>(asm_ + AT_V);
    float*  XNEW = reinterpret_cast<float*>(asm_ + AT_XNEW);
    float*  SC   = reinterpret_cast<float*>(asm_ + AT_SC);
    float*  SK   = reinterpret_cast<float*>(asm_ + AT_SK);
    float*  PSW  = reinterpret_cast<float*>(asm_ + AT_PSW);

    const int tid = threadIdx.x;
    const int wid = tid >> 5;
    const int lane = tid & 31;
    const size_t r0 = (size_t)blockIdx.x * 2 * NJ;   // first row of frame pair

    {
        const uint4* src = reinterpret_cast<const uint4*>(g_lr + r0 * 512);
        uint4* d = reinterpret_cast<uint4*>(LR);
        for (int i = tid; i < 2 * NJ * 512 * 2 / 16; i += 256) d[i] = src[i];
        const uint4* sv = reinterpret_cast<const uint4*>(g_v + r0 * DM);
        uint4* dv = reinterpret_cast<uint4*>(V);
        for (int i = tid; i < 2 * NJ * DM * 4 / 16; i += 256) dv[i] = sv[i];
    }
    if (tid < 2 * NJ) SK[tid] = g_skip[r0 + tid];
    if (tid < DM) PSW[tid] = psw[tid];
    __syncthreads();

    // ---- scores: 196 tasks (2 frames x 2 heads x 49 edges), 4 lanes/task ----
    // Uniform trip count (4 rounds for ALL threads) so the intra-task shuffles
    // below always execute convergently; tail tasks are clamped + predicated.
    {
        const int sub = tid & 3;
        const int t0 = tid >> 2;                    // 0..63
#pragma unroll
        for (int base = 0; base < 256; base += 64) {
            int tt = t0 + base;                      // 0..255, same count all threads
            int ttc = (tt < 196) ? tt : 195;         // clamp for safe redundant work
            int f = (ttc >= 98);
            int t = ttc - 98 * f;
            int h = (t >= NEDGE);
            int e = t - h * NEDGE;
            int i = c_erow[e];
            int j = c_nbr[e];
            const __half2* lp = reinterpret_cast<const __half2*>(
                LR + f * NJ * 512 + i * 512 + h * 128);
            const __half2* rp = reinterpret_cast<const __half2*>(
                LR + f * NJ * 512 + j * 512 + 256 + h * 128);
            float acc = 0.f;
#pragma unroll
            for (int qq = 0; qq < 16; qq++) {
                int d2 = sub * 16 + qq;
                float2 l2 = __half22float2(lp[d2]);
                float2 r2 = __half22float2(rp[d2]);
                float u0 = l2.x + r2.x, u1 = l2.y + r2.y;
                float2 pw = *reinterpret_cast<const float2*>(&PSW[d2 * 2]);
                acc = fmaf(fmaxf(u0, 0.2f * u0), pw.x, acc);
                acc = fmaf(fmaxf(u1, 0.2f * u1), pw.y, acc);
            }
            acc += __shfl_xor_sync(0xffffffffu, acc, 1);
            acc += __shfl_xor_sync(0xffffffffu, acc, 2);
            if (sub == 0 && tt < 196) SC[tt] = acc;
        }
    }
    __syncthreads();

    // ---- softmax: 68 (frame,head,row) tasks ----
    if (tid < 68) {
        int f = (tid >= 34);
        int t34 = tid - 34 * f;
        int h = (t34 >= NJ);
        int i = t34 - h * NJ;
        float* sc = SC + f * 98 + h * NEDGE;
        int rs = c_row_start[i], re = c_row_start[i + 1];
        float m = -1e30f;
        for (int e = rs; e < re; e++) m = fmaxf(m, sc[e]);
        float s = 0.f;
        for (int e = rs; e < re; e++) s += __expf(sc[e] - m);
        float inv = 1.0f / s;
        for (int e = rs; e < re; e++) sc[e] = __expf(sc[e] - m) * inv;
    }
    __syncthreads();

    // ---- aggregate + gelu + mix; thread owns (frame, column) ----
    {
        const int f = tid >> 7, c = tid & 127;
        const int h = c >> 6, d = c & 63;
        const float* sc = SC + f * 98 + h * NEDGE;
        const float* vf = V + f * NJ * DM + h * 64 + d;
        const size_t fr0 = r0 + f * NJ;
#pragma unroll 1
        for (int j = 0; j < NJ; j++) {
            int rs = c_row_start[j], re = c_row_start[j + 1];
            float acc = 0.f;
            for (int e = rs; e < re; e++)
                acc = fmaf(sc[e], vf[(int)c_nbr[e] * DM], acc);
            float gl = 0.5f * acc * (1.0f + erff(acc * 0.70710678118654752f));
            float sk = SK[f * NJ + j];
            float val = (1.0f - sk) * gl + sk * g_X0[(fr0 + j) * DM + c];
            if (last) out[(fr0 + j) * DM + c] = val;
            else      XNEW[(f * NJ + j) * DM + c] = val;
        }
    }
    if (last) return;
    __syncthreads();

    // ---- fused next-iter LN + skip + bf16 split (warp per row, 34 rows) ----
    for (int rr = wid; rr < 2 * NJ; rr += 8) {
        float4 v = *reinterpret_cast<const float4*>(&XNEW[rr * DM + lane * 4]);
        ln_split_row(v.x, v.y, v.z, v.w, lane, r0 + rr, lg, lb);
    }
}

// ---------------- launch ----------------
extern "C" void kernel_launch(void* const* d_in, const int* in_sizes, int n_in,
                              void* d_out, int out_size) {
    const float* x   = (const float*)d_in[0];
    const float* og  = (const float*)d_in[1];
    const float* ob  = (const float*)d_in[2];
    const float* lg  = (const float*)d_in[3];
    const float* lb  = (const float*)d_in[4];
    const float* aw  = (const float*)d_in[5];
    const float* ab  = (const float*)d_in[6];
    const float* w1  = (const float*)d_in[7];
    const float* b1  = (const float*)d_in[8];
    const float* w2  = (const float*)d_in[9];
    const float* b2  = (const float*)d_in[10];
    const float* psw = (const float*)d_in[11];
    const float* vw  = (const float*)d_in[13];
    const float* vb  = (const float*)d_in[14];
    float* out = (float*)d_out;

    cudaFuncSetAttribute(gemm_kernel,
                         cudaFuncAttributeMaxDynamicSharedMemorySize, GEMM_SMEM);
    cudaFuncSetAttribute(attn_fused_kernel,
                         cudaFuncAttributeMaxDynamicSharedMemorySize, ATTN_SMEM);

    prep_kernel<<<(640 * 128 + 255) / 256, 256>>>(w1, b1, w2, b2, vw, vb, lg, lb, aw, ab);
    outer_fused_kernel<<<NROWS / 8, 256>>>(x, og, ob, lg, lb);

    for (int it = 0; it < 4; it++) {
        gemm_kernel<<<dim3(MTILES, NCHUNK), 256, GEMM_SMEM>>>();
        attn_fused_kernel<<<NFR / 2, 256, ATTN_SMEM>>>(psw, lg, lb, out, it == 3);
    }
}

// round 11
// speedup vs baseline: 1.1362x; 1.1362x over previous
#include <cuda_runtime.h>
#include <cuda_fp16.h>
#include <cuda_bf16.h>
#include <cstdint>

#define NJ 17
#define DM 128
#define NEDGE 49
#define NROWS 66096          // 3888 * 17
#define NFR 3888
#define MTILES 517           // ceil(66096/128)
#define NCHUNK 10            // 640 / 64
#define KSTRIDE 136          // smem row stride (bf16 elems), conflict-free ldmatrix

// ---------------- device scratch ----------------
__device__ float g_XS[(size_t)NROWS * DM];
__device__ float g_X0[(size_t)NROWS * DM];
__device__ float g_skip[NROWS];
__device__ __align__(16) __nv_bfloat16 g_ah[(size_t)MTILES * 128 * 128];
__device__ __align__(16) __nv_bfloat16 g_al[(size_t)MTILES * 128 * 128];
__device__ __align__(16) __nv_bfloat16 g_bh[640 * 128];
__device__ __align__(16) __nv_bfloat16 g_bl[640 * 128];
__device__ float g_bias[640];
__device__ float g_lgaw[DM];         // lg[k]*aw[k]
__device__ float g_c1;               // sum lg*aw
__device__ float g_c2;               // sum lb*aw + ab
__device__ __align__(16) __half g_lr[(size_t)NROWS * 512];
__device__ __align__(16) float g_v[(size_t)NROWS * DM];

// ---------------- adjacency ----------------
__device__ __constant__ int c_row_start[18] =
    {0,4,7,10,12,15,18,20,23,28,31,33,36,39,41,44,47,49};
__device__ __constant__ signed char c_nbr[NEDGE] = {
    0,1,4,7,  0,1,2,  1,2,3,  2,3,  0,4,5,  4,5,6,  5,6,  0,7,8,
    7,8,9,11,14,  8,9,10,  9,10,  8,11,12,  11,12,13,  12,13,
    8,14,15,  14,15,16,  15,16};
__device__ __constant__ signed char c_erow[NEDGE] = {
    0,0,0,0,  1,1,1,  2,2,2,  3,3,  4,4,4,  5,5,5,  6,6,  7,7,7,
    8,8,8,8,8,  9,9,9,  10,10,  11,11,11,  12,12,12,  13,13,
    14,14,14,  15,15,15,  16,16};

// ---------------- helpers ----------------
__device__ __forceinline__ uint32_t smem_u32(const void* p) {
    uint32_t a;
    asm("{ .reg .u64 t; cvta.to.shared.u64 t, %1; cvt.u32.u64 %0, t; }" : "=r"(a) : "l"(p));
    return a;
}
__device__ __forceinline__ void ldm4(uint32_t* r, uint32_t addr) {
    asm volatile("ldmatrix.sync.aligned.m8n8.x4.shared.b16 {%0,%1,%2,%3}, [%4];"
                 : "=r"(r[0]), "=r"(r[1]), "=r"(r[2]), "=r"(r[3]) : "r"(addr));
}
__device__ __forceinline__ void mma_bf16(float* c, const uint32_t* a, const uint32_t* b) {
    asm volatile("mma.sync.aligned.m16n8k16.row.col.f32.bf16.bf16.f32 "
                 "{%0,%1,%2,%3}, {%4,%5,%6,%7}, {%8,%9}, {%0,%1,%2,%3};"
                 : "+f"(c[0]), "+f"(c[1]), "+f"(c[2]), "+f"(c[3])
                 : "r"(a[0]), "r"(a[1]), "r"(a[2]), "r"(a[3]), "r"(b[0]), "r"(b[1]));
}

// LN + skip + bf16 hi/lo split for one row held by one warp.
// Single interleaved 3-way warp reduction: s=Σx, q=Σx², t=Σ x·(lg·aw).
__device__ __forceinline__ void ln_split_row(
    float v0, float v1, float v2, float v3, int lane, size_t grow,
    const float* __restrict__ lg, const float* __restrict__ lb)
{
    int k = lane * 4;
    float s = v0 + v1 + v2 + v3;
    float q = v0 * v0 + v1 * v1 + v2 * v2 + v3 * v3;
    float t = v0 * g_lgaw[k] + v1 * g_lgaw[k + 1]
            + v2 * g_lgaw[k + 2] + v3 * g_lgaw[k + 3];
#pragma unroll
    for (int o = 16; o; o >>= 1) {
        s += __shfl_xor_sync(0xffffffffu, s, o);
        q += __shfl_xor_sync(0xffffffffu, q, o);
        t += __shfl_xor_sync(0xffffffffu, t, o);
    }
    float m = s * (1.0f / 128.0f);
    float var = q * (1.0f / 128.0f) - m * m;
    float rstd = rsqrtf(var + 1e-5f);
    if (lane == 0) {
        float ad = rstd * (t - m * g_c1) + g_c2;
        g_skip[grow] = 1.0f / (1.0f + __expf(-ad));
    }
    float n0 = (v0 - m) * rstd * __ldg(lg + k)     + __ldg(lb + k);
    float n1 = (v1 - m) * rstd * __ldg(lg + k + 1) + __ldg(lb + k + 1);
    float n2 = (v2 - m) * rstd * __ldg(lg + k + 2) + __ldg(lb + k + 2);
    float n3 = (v3 - m) * rstd * __ldg(lg + k + 3) + __ldg(lb + k + 3);

    __nv_bfloat16 h0 = __float2bfloat16(n0), h1 = __float2bfloat16(n1);
    __nv_bfloat16 h2 = __float2bfloat16(n2), h3 = __float2bfloat16(n3);
    __nv_bfloat162 ph01 = __halves2bfloat162(h0, h1);
    __nv_bfloat162 ph23 = __halves2bfloat162(h2, h3);
    __nv_bfloat162 pl01 = __halves2bfloat162(
        __float2bfloat16(n0 - __bfloat162float(h0)),
        __float2bfloat16(n1 - __bfloat162float(h1)));
    __nv_bfloat162 pl23 = __halves2bfloat162(
        __float2bfloat16(n2 - __bfloat162float(h2)),
        __float2bfloat16(n3 - __bfloat162float(h3)));
    uint2 uh, ul;
    uh.x = *reinterpret_cast<uint32_t*>(&ph01);
    uh.y = *reinterpret_cast<uint32_t*>(&ph23);
    ul.x = *reinterpret_cast<uint32_t*>(&pl01);
    ul.y = *reinterpret_cast<uint32_t*>(&pl23);
    *reinterpret_cast<uint2*>(g_ah + grow * 128 + k) = uh;
    *reinterpret_cast<uint2*>(g_al + grow * 128 + k) = ul;
}

// ---------------- prologue: weight split + skip-gate constants ----------------
__global__ void prep_kernel(const float* __restrict__ w1, const float* __restrict__ b1,
                            const float* __restrict__ w2, const float* __restrict__ b2,
                            const float* __restrict__ vw, const float* __restrict__ vb,
                            const float* __restrict__ lg, const float* __restrict__ lb,
                            const float* __restrict__ aw, const float* __restrict__ ab)
{
    int idx = blockIdx.x * blockDim.x + threadIdx.x;
    if (idx < 640 * 128) {
        int n = idx >> 7;
        int k = idx & 127;
        float w = (n < 256) ? w1[k * 256 + n]
                : (n < 512) ? w2[k * 256 + (n - 256)]
                            : vw[k * 128 + (n - 512)];
        __nv_bfloat16 h = __float2bfloat16(w);
        __nv_bfloat16 l = __float2bfloat16(w - __bfloat162float(h));
        g_bh[idx] = h;
        g_bl[idx] = l;
    }
    if (idx < 640) {
        g_bias[idx] = (idx < 256) ? b1[idx]
                    : (idx < 512) ? b2[idx - 256]
                                  : vb[idx - 512];
    }
    if (idx < DM) g_lgaw[idx] = lg[idx] * aw[idx];
    if (idx == 0) {
        float c1 = 0.f, c2 = 0.f;
        for (int k = 0; k < DM; k++) { c1 += lg[k] * aw[k]; c2 += lb[k] * aw[k]; }
        g_c1 = c1;
        g_c2 = c2 + ab[0];
    }
}

// ---------------- outer LN + first inner LN/split: x -> g_X0, g_ah/al, g_skip ----------------
__global__ __launch_bounds__(256) void outer_fused_kernel(
    const float* __restrict__ x,
    const float* __restrict__ og, const float* __restrict__ ob,
    const float* __restrict__ lg, const float* __restrict__ lb)
{
    size_t row = (size_t)blockIdx.x * 8 + (threadIdx.x >> 5);
    int lane = threadIdx.x & 31;
    float4 v = *reinterpret_cast<const float4*>(x + row * DM + lane * 4);
    float s = v.x + v.y + v.z + v.w;
    float q = v.x * v.x + v.y * v.y + v.z * v.z + v.w * v.w;
#pragma unroll
    for (int o = 16; o; o >>= 1) {
        s += __shfl_xor_sync(0xffffffffu, s, o);
        q += __shfl_xor_sync(0xffffffffu, q, o);
    }
    float m = s * (1.0f / 128.0f);
    float rstd = rsqrtf(q * (1.0f / 128.0f) - m * m + 1e-5f);
    int k = lane * 4;
    float4 o;
    o.x = (v.x - m) * rstd * __ldg(og + k)     + __ldg(ob + k);
    o.y = (v.y - m) * rstd * __ldg(og + k + 1) + __ldg(ob + k + 1);
    o.z = (v.z - m) * rstd * __ldg(og + k + 2) + __ldg(ob + k + 2);
    o.w = (v.w - m) * rstd * __ldg(og + k + 3) + __ldg(ob + k + 3);
    *reinterpret_cast<float4*>(g_X0 + row * DM + k) = o;
    ln_split_row(o.x, o.y, o.z, o.w, lane, row, lg, lb);
}

// ---------------- per-iter LN: g_XS -> g_ah/al + skip (one warp per row) ----------------
__global__ __launch_bounds__(256) void ln_kernel(
    const float* __restrict__ lg, const float* __restrict__ lb)
{
    size_t row = (size_t)blockIdx.x * 8 + (threadIdx.x >> 5);
    int lane = threadIdx.x & 31;
    float4 v = *reinterpret_cast<const float4*>(g_XS + row * DM + lane * 4);
    ln_split_row(v.x, v.y, v.z, v.w, lane, row, lg, lb);
}

// ---------------- GEMM: 128M x 64N tile, K=128 one-shot, split-bf16 ----------------
// l,r chunks (0-7): 2-term (Ah+Al)@Bh; v chunks (8-9): 3-term (+ Ah@Bl).
#define TILE_A (128 * KSTRIDE)
#define TILE_B (64 * KSTRIDE)
#define GEMM_SMEM ((2 * TILE_A + 2 * TILE_B) * 2)   // 104448 bytes -> 2 CTAs/SM

template<bool FULL>
__device__ __forceinline__ void gemm_mainloop(
    uint32_t aBaseH, uint32_t aBaseL, uint32_t bBaseH, uint32_t bBaseL,
    float acc[2][4][4])
{
#pragma unroll 2
    for (int k0 = 0; k0 < 128; k0 += 16) {
        uint32_t ah[2][4], al[2][4], bh[4][2], bl[4][2];
#pragma unroll
        for (int mt = 0; mt < 2; mt++) {
            uint32_t off = (uint32_t)(mt * 16 * KSTRIDE + k0) * 2;
            ldm4(ah[mt], aBaseH + off);
            ldm4(al[mt], aBaseL + off);
        }
#pragma unroll
        for (int p = 0; p < 2; p++) {
            uint32_t off = (uint32_t)(p * 16 * KSTRIDE + k0) * 2;
            uint32_t t[4];
            ldm4(t, bBaseH + off);
            bh[2 * p][0] = t[0]; bh[2 * p][1] = t[1];
            bh[2 * p + 1][0] = t[2]; bh[2 * p + 1][1] = t[3];
            if (FULL) {
                ldm4(t, bBaseL + off);
                bl[2 * p][0] = t[0]; bl[2 * p][1] = t[1];
                bl[2 * p + 1][0] = t[2]; bl[2 * p + 1][1] = t[3];
            }
        }
#pragma unroll
        for (int mt = 0; mt < 2; mt++)
#pragma unroll
            for (int nt = 0; nt < 4; nt++) {
                mma_bf16(acc[mt][nt], ah[mt], bh[nt]);
                mma_bf16(acc[mt][nt], al[mt], bh[nt]);
                if (FULL) mma_bf16(acc[mt][nt], ah[mt], bl[nt]);
            }
    }
}

__global__ __launch_bounds__(256) void gemm_kernel()
{
    extern __shared__ __nv_bfloat16 sm[];
    __nv_bfloat16* sAh = sm;
    __nv_bfloat16* sAl = sm + TILE_A;
    __nv_bfloat16* sBh = sm + 2 * TILE_A;
    __nv_bfloat16* sBl = sm + 2 * TILE_A + TILE_B;

    const int tid = threadIdx.x;
    const int mtile = blockIdx.x;
    const int chunk = blockIdx.y;
    const bool full = (chunk >= 8);        // v chunks need the Bl correction

    {
        const uint4* gAh = reinterpret_cast<const uint4*>(g_ah + (size_t)mtile * 128 * 128);
        const uint4* gAl = reinterpret_cast<const uint4*>(g_al + (size_t)mtile * 128 * 128);
        for (int i = tid; i < 2048; i += 256) {
            int row = i >> 4, c = i & 15;
            int d = row * KSTRIDE + c * 8;
            *reinterpret_cast<uint4*>(sAh + d) = gAh[i];
            *reinterpret_cast<uint4*>(sAl + d) = gAl[i];
        }
        const uint4* gBh = reinterpret_cast<const uint4*>(g_bh + (size_t)chunk * 64 * 128);
        const uint4* gBl = reinterpret_cast<const uint4*>(g_bl + (size_t)chunk * 64 * 128);
        for (int i = tid; i < 1024; i += 256) {
            int row = i >> 4, c = i & 15;
            int d = row * KSTRIDE + c * 8;
            *reinterpret_cast<uint4*>(sBh + d) = gBh[i];
            if (full) *reinterpret_cast<uint4*>(sBl + d) = gBl[i];
        }
    }
    __syncthreads();

    const int wid = tid >> 5, lane = tid & 31;
    const int wm = wid >> 1, wn = wid & 1;
    const int mBase = wm * 32, nBase = wn * 32;
    const int g = lane >> 3, r = lane & 7;

    const int a_row = r + (g & 1) * 8, a_k = (g >> 1) * 8;
    const int b_n = r + (g >> 1) * 8, b_k = (g & 1) * 8;
    uint32_t aBaseH = smem_u32(sAh) + ((mBase + a_row) * KSTRIDE + a_k) * 2;
    uint32_t aBaseL = smem_u32(sAl) + ((mBase + a_row) * KSTRIDE + a_k) * 2;
    uint32_t bBaseH = smem_u32(sBh) + ((nBase + b_n) * KSTRIDE + b_k) * 2;
    uint32_t bBaseL = smem_u32(sBl) + ((nBase + b_n) * KSTRIDE + b_k) * 2;

    float acc[2][4][4];
#pragma unroll
    for (int mt = 0; mt < 2; mt++)
#pragma unroll
        for (int nt = 0; nt < 4; nt++)
#pragma unroll
            for (int q = 0; q < 4; q++) acc[mt][nt][q] = 0.f;

    if (full) gemm_mainloop<true>(aBaseH, aBaseL, bBaseH, bBaseL, acc);
    else      gemm_mainloop<false>(aBaseH, aBaseL, bBaseH, bBaseL, acc);

    const int qrow = lane >> 2, qcol = (lane & 3) * 2;
#pragma unroll
    for (int mt = 0; mt < 2; mt++) {
#pragma unroll
        for (int nt = 0; nt < 4; nt++) {
            int row0 = mtile * 128 + mBase + mt * 16 + qrow;
            int col = nBase + nt * 8 + qcol;
            int gcol = chunk * 64 + col;
            float b0 = g_bias[gcol], b1 = g_bias[gcol + 1];
            float c0 = acc[mt][nt][0] + b0, c1 = acc[mt][nt][1] + b1;
            float c2 = acc[mt][nt][2] + b0, c3 = acc[mt][nt][3] + b1;
            if (!full) {
                if (row0 < NROWS)
                    *reinterpret_cast<__half2*>(&g_lr[(size_t)row0 * 512 + gcol]) =
                        __halves2half2(__float2half(c0), __float2half(c1));
                if (row0 + 8 < NROWS)
                    *reinterpret_cast<__half2*>(&g_lr[(size_t)(row0 + 8) * 512 + gcol]) =
                        __halves2half2(__float2half(c2), __float2half(c3));
            } else {
                int vc = gcol - 512;
                if (row0 < NROWS) {
                    float2 o; o.x = c0; o.y = c1;
                    *reinterpret_cast<float2*>(&g_v[(size_t)row0 * DM + vc]) = o;
                }
                if (row0 + 8 < NROWS) {
                    float2 o; o.x = c2; o.y = c3;
                    *reinterpret_cast<float2*>(&g_v[(size_t)(row0 + 8) * DM + vc]) = o;
                }
            }
        }
    }
}

// ---------------- attention: lean, 1 frame / 128-thread CTA ----------------
__global__ __launch_bounds__(128) void attn_kernel(const float* __restrict__ psw,
                                                   float* __restrict__ dst)
{
    __shared__ __align__(16) __half LR[NJ * 512];      // 17408 B
    __shared__ __align__(16) float V[NJ * DM];         //  8704 B
    __shared__ __align__(16) float SC[2 * NEDGE];
    __shared__ __align__(16) float SK[NJ];
    __shared__ __align__(16) float PSW[DM];            // float2-read: must be 8B+ aligned

    const int tid = threadIdx.x;
    const size_t r0 = (size_t)blockIdx.x * NJ;

    {
        const uint4* src = reinterpret_cast<const uint4*>(g_lr + r0 * 512);
        uint4* d = reinterpret_cast<uint4*>(LR);
        for (int i = tid; i < NJ * 512 * 2 / 16; i += 128) d[i] = src[i];
        const uint4* sv = reinterpret_cast<const uint4*>(g_v + r0 * DM);
        uint4* dv = reinterpret_cast<uint4*>(V);
        for (int i = tid; i < NJ * DM * 4 / 16; i += 128) dv[i] = sv[i];
    }
    if (tid < NJ) SK[tid] = g_skip[r0 + tid];
    if (tid < DM) PSW[tid] = psw[tid];
    __syncthreads();

    // ---- scores: 98 tasks (2 heads x 49 edges), 4 lanes/task, uniform trips ----
    {
        const int sub = tid & 3;
        const int t0 = tid >> 2;                  // 0..31
#pragma unroll
        for (int base = 0; base < 128; base += 32) {
            int tt = t0 + base;                    // 0..127, same count all threads
            int ttc = (tt < 98) ? tt : 97;         // clamp (redundant work on tail)
            int h = (ttc >= NEDGE);
            int e = ttc - h * NEDGE;
            int i = c_erow[e];
            int j = c_nbr[e];
            const __half2* lp = reinterpret_cast<const __half2*>(LR + i * 512 + h * 128);
            const __half2* rp = reinterpret_cast<const __half2*>(LR + j * 512 + 256 + h * 128);
            float acc = 0.f;
#pragma unroll
            for (int qq = 0; qq < 16; qq++) {
                int d2 = sub * 16 + qq;
                float2 l2 = __half22float2(lp[d2]);
                float2 r2 = __half22float2(rp[d2]);
                float u0 = l2.x + r2.x, u1 = l2.y + r2.y;
                float2 pw = *reinterpret_cast<const float2*>(&PSW[d2 * 2]);
                acc = fmaf(fmaxf(u0, 0.2f * u0), pw.x, acc);
                acc = fmaf(fmaxf(u1, 0.2f * u1), pw.y, acc);
            }
            acc += __shfl_xor_sync(0xffffffffu, acc, 1);
            acc += __shfl_xor_sync(0xffffffffu, acc, 2);
            if (sub == 0 && tt < 98) SC[tt] = acc;
        }
    }
    __syncthreads();

    // ---- softmax: 34 (head,row) tasks ----
    if (tid < 34) {
        int h = (tid >= NJ);
        int i = tid - h * NJ;
        float* sc = SC + h * NEDGE;
        int rs = c_row_start[i], re = c_row_start[i + 1];
        float m = -1e30f;
        for (int e = rs; e < re; e++) m = fmaxf(m, sc[e]);
        float s = 0.f;
        for (int e = rs; e < re; e++) s += __expf(sc[e] - m);
        float inv = 1.0f / s;
        for (int e = rs; e < re; e++) sc[e] = __expf(sc[e] - m) * inv;
    }
    __syncthreads();

    // ---- aggregate + gelu + mix; thread owns column tid of every row ----
    {
        const int h = tid >> 6, d = tid & 63;
        const float* sc = SC + h * NEDGE;
        const float* vf = V + h * 64 + d;
#pragma unroll 1
        for (int j = 0; j < NJ; j++) {
            int rs = c_row_start[j], re = c_row_start[j + 1];
            float acc = 0.f;
            for (int e = rs; e < re; e++)
                acc = fmaf(sc[e], vf[(int)c_nbr[e] * DM], acc);
            float gl = 0.5f * acc * (1.0f + erff(acc * 0.70710678118654752f));
            float sk = SK[j];
            dst[(r0 + j) * DM + tid] = (1.0f - sk) * gl + sk * g_X0[(r0 + j) * DM + tid];
        }
    }
}

// ---------------- launch ----------------
extern "C" void kernel_launch(void* const* d_in, const int* in_sizes, int n_in,
                              void* d_out, int out_size) {
    const float* x   = (const float*)d_in[0];
    const float* og  = (const float*)d_in[1];
    const float* ob  = (const float*)d_in[2];
    const float* lg  = (const float*)d_in[3];
    const float* lb  = (const float*)d_in[4];
    const float* aw  = (const float*)d_in[5];
    const float* ab  = (const float*)d_in[6];
    const float* w1  = (const float*)d_in[7];
    const float* b1  = (const float*)d_in[8];
    const float* w2  = (const float*)d_in[9];
    const float* b2  = (const float*)d_in[10];
    const float* psw = (const float*)d_in[11];
    const float* vw  = (const float*)d_in[13];
    const float* vb  = (const float*)d_in[14];
    float* out = (float*)d_out;

    cudaFuncSetAttribute(gemm_kernel,
                         cudaFuncAttributeMaxDynamicSharedMemorySize, GEMM_SMEM);

    prep_kernel<<<(640 * 128 + 255) / 256, 256>>>(w1, b1, w2, b2, vw, vb, lg, lb, aw, ab);
    outer_fused_kernel<<<NROWS / 8, 256>>>(x, og, ob, lg, lb);

    float* g_xs_ptr = nullptr;
    cudaGetSymbolAddress((void**)&g_xs_ptr, g_XS);

    for (int it = 0; it < 4; it++) {
        gemm_kernel<<<dim3(MTILES, NCHUNK), 256, GEMM_SMEM>>>();
        attn_kernel<<<NFR, 128>>>(psw, (it == 3) ? out : g_xs_ptr);
        if (it < 3) ln_kernel<<<NROWS / 8, 256>>>(lg, lb);
    }
}

// round 13
// speedup vs baseline: 1.2897x; 1.1351x over previous
#include <cuda_runtime.h>
#include <cuda_fp16.h>
#include <cuda_bf16.h>
#include <cstdint>

#define NJ 17
#define DM 128
#define NEDGE 49
#define NROWS 66096          // 3888 * 17
#define NFR 3888
#define MTILES 517           // ceil(66096/128)
#define NCHUNK 10            // 640 / 64
#define KSTRIDE 136          // smem row stride (bf16 elems), conflict-free ldmatrix
#define NTASK (NFR * 34)     // (frame, head, row) score tasks

// ---------------- device scratch ----------------
__device__ float g_XS[(size_t)NROWS * DM];
__device__ float g_X0[(size_t)NROWS * DM];
__device__ float g_skip[NROWS];
__device__ __align__(16) __nv_bfloat16 g_ah[(size_t)MTILES * 128 * 128];
__device__ __align__(16) __nv_bfloat16 g_al[(size_t)MTILES * 128 * 128];
__device__ __align__(16) __nv_bfloat16 g_bh[640 * 128];
__device__ __align__(16) __nv_bfloat16 g_bl[640 * 128];
__device__ float g_bias[640];
__device__ float g_lgaw[DM];         // lg[k]*aw[k]
__device__ float g_c1;               // sum lg*aw
__device__ float g_c2;               // sum lb*aw + ab
__device__ __align__(16) __half g_lr[(size_t)NROWS * 512];
__device__ __align__(16) float g_v[(size_t)NROWS * DM];
__device__ float g_sc[(size_t)NFR * 98];   // softmaxed attention probs

// ---------------- adjacency ----------------
__device__ __constant__ int c_row_start[18] =
    {0,4,7,10,12,15,18,20,23,28,31,33,36,39,41,44,47,49};
__device__ __constant__ signed char c_nbr[NEDGE] = {
    0,1,4,7,  0,1,2,  1,2,3,  2,3,  0,4,5,  4,5,6,  5,6,  0,7,8,
    7,8,9,11,14,  8,9,10,  9,10,  8,11,12,  11,12,13,  12,13,
    8,14,15,  14,15,16,  15,16};
__device__ __constant__ signed char c_erow[NEDGE] = {
    0,0,0,0,  1,1,1,  2,2,2,  3,3,  4,4,4,  5,5,5,  6,6,  7,7,7,
    8,8,8,8,8,  9,9,9,  10,10,  11,11,11,  12,12,12,  13,13,
    14,14,14,  15,15,15,  16,16};

// ---------------- helpers ----------------
__device__ __forceinline__ uint32_t smem_u32(const void* p) {
    uint32_t a;
    asm("{ .reg .u64 t; cvta.to.shared.u64 t, %1; cvt.u32.u64 %0, t; }" : "=r"(a) : "l"(p));
    return a;
}
__device__ __forceinline__ void ldm4(uint32_t* r, uint32_t addr) {
    asm volatile("ldmatrix.sync.aligned.m8n8.x4.shared.b16 {%0,%1,%2,%3}, [%4];"
                 : "=r"(r[0]), "=r"(r[1]), "=r"(r[2]), "=r"(r[3]) : "r"(addr));
}
__device__ __forceinline__ void mma_bf16(float* c, const uint32_t* a, const uint32_t* b) {
    asm volatile("mma.sync.aligned.m16n8k16.row.col.f32.bf16.bf16.f32 "
                 "{%0,%1,%2,%3}, {%4,%5,%6,%7}, {%8,%9}, {%0,%1,%2,%3};"
                 : "+f"(c[0]), "+f"(c[1]), "+f"(c[2]), "+f"(c[3])
                 : "r"(a[0]), "r"(a[1]), "r"(a[2]), "r"(a[3]), "r"(b[0]), "r"(b[1]));
}

// LN + skip + bf16 hi/lo split for one row held by one warp.
__device__ __forceinline__ void ln_split_row(
    float v0, float v1, float v2, float v3, int lane, size_t grow,
    const float* __restrict__ lg, const float* __restrict__ lb)
{
    int k = lane * 4;
    float s = v0 + v1 + v2 + v3;
    float q = v0 * v0 + v1 * v1 + v2 * v2 + v3 * v3;
    float t = v0 * g_lgaw[k] + v1 * g_lgaw[k + 1]
            + v2 * g_lgaw[k + 2] + v3 * g_lgaw[k + 3];
#pragma unroll
    for (int o = 16; o; o >>= 1) {
        s += __shfl_xor_sync(0xffffffffu, s, o);
        q += __shfl_xor_sync(0xffffffffu, q, o);
        t += __shfl_xor_sync(0xffffffffu, t, o);
    }
    float m = s * (1.0f / 128.0f);
    float var = q * (1.0f / 128.0f) - m * m;
    float rstd = rsqrtf(var + 1e-5f);
    if (lane == 0) {
        float ad = rstd * (t - m * g_c1) + g_c2;
        g_skip[grow] = 1.0f / (1.0f + __expf(-ad));
    }
    float n0 = (v0 - m) * rstd * __ldg(lg + k)     + __ldg(lb + k);
    float n1 = (v1 - m) * rstd * __ldg(lg + k + 1) + __ldg(lb + k + 1);
    float n2 = (v2 - m) * rstd * __ldg(lg + k + 2) + __ldg(lb + k + 2);
    float n3 = (v3 - m) * rstd * __ldg(lg + k + 3) + __ldg(lb + k + 3);

    __nv_bfloat16 h0 = __float2bfloat16(n0), h1 = __float2bfloat16(n1);
    __nv_bfloat16 h2 = __float2bfloat16(n2), h3 = __float2bfloat16(n3);
    __nv_bfloat162 ph01 = __halves2bfloat162(h0, h1);
    __nv_bfloat162 ph23 = __halves2bfloat162(h2, h3);
    __nv_bfloat162 pl01 = __halves2bfloat162(
        __float2bfloat16(n0 - __bfloat162float(h0)),
        __float2bfloat16(n1 - __bfloat162float(h1)));
    __nv_bfloat162 pl23 = __halves2bfloat162(
        __float2bfloat16(n2 - __bfloat162float(h2)),
        __float2bfloat16(n3 - __bfloat162float(h3)));
    uint2 uh, ul;
    uh.x = *reinterpret_cast<uint32_t*>(&ph01);
    uh.y = *reinterpret_cast<uint32_t*>(&ph23);
    ul.x = *reinterpret_cast<uint32_t*>(&pl01);
    ul.y = *reinterpret_cast<uint32_t*>(&pl23);
    *reinterpret_cast<uint2*>(g_ah + grow * 128 + k) = uh;
    *reinterpret_cast<uint2*>(g_al + grow * 128 + k) = ul;
}

// ---------------- prologue: weight split + skip-gate constants ----------------
__global__ void prep_kernel(const float* __restrict__ w1, const float* __restrict__ b1,
                            const float* __restrict__ w2, const float* __restrict__ b2,
                            const float* __restrict__ vw, const float* __restrict__ vb,
                            const float* __restrict__ lg, const float* __restrict__ lb,
                            const float* __restrict__ aw, const float* __restrict__ ab)
{
    int idx = blockIdx.x * blockDim.x + threadIdx.x;
    if (idx < 640 * 128) {
        int n = idx >> 7;
        int k = idx & 127;
        float w = (n < 256) ? w1[k * 256 + n]
                : (n < 512) ? w2[k * 256 + (n - 256)]
                            : vw[k * 128 + (n - 512)];
        __nv_bfloat16 h = __float2bfloat16(w);
        __nv_bfloat16 l = __float2bfloat16(w - __bfloat162float(h));
        g_bh[idx] = h;
        g_bl[idx] = l;
    }
    if (idx < 640) {
        g_bias[idx] = (idx < 256) ? b1[idx]
                    : (idx < 512) ? b2[idx - 256]
                                  : vb[idx - 512];
    }
    if (idx < DM) g_lgaw[idx] = lg[idx] * aw[idx];
    if (idx == 0) {
        float c1 = 0.f, c2 = 0.f;
        for (int k = 0; k < DM; k++) { c1 += lg[k] * aw[k]; c2 += lb[k] * aw[k]; }
        g_c1 = c1;
        g_c2 = c2 + ab[0];
    }
}

// ---------------- outer LN + first inner LN/split ----------------
__global__ __launch_bounds__(256) void outer_fused_kernel(
    const float* __restrict__ x,
    const float* __restrict__ og, const float* __restrict__ ob,
    const float* __restrict__ lg, const float* __restrict__ lb)
{
    size_t row = (size_t)blockIdx.x * 8 + (threadIdx.x >> 5);
    int lane = threadIdx.x & 31;
    float4 v = *reinterpret_cast<const float4*>(x + row * DM + lane * 4);
    float s = v.x + v.y + v.z + v.w;
    float q = v.x * v.x + v.y * v.y + v.z * v.z + v.w * v.w;
#pragma unroll
    for (int o = 16; o; o >>= 1) {
        s += __shfl_xor_sync(0xffffffffu, s, o);
        q += __shfl_xor_sync(0xffffffffu, q, o);
    }
    float m = s * (1.0f / 128.0f);
    float rstd = rsqrtf(q * (1.0f / 128.0f) - m * m + 1e-5f);
    int k = lane * 4;
    float4 o;
    o.x = (v.x - m) * rstd * __ldg(og + k)     + __ldg(ob + k);
    o.y = (v.y - m) * rstd * __ldg(og + k + 1) + __ldg(ob + k + 1);
    o.z = (v.z - m) * rstd * __ldg(og + k + 2) + __ldg(ob + k + 2);
    o.w = (v.w - m) * rstd * __ldg(og + k + 3) + __ldg(ob + k + 3);
    *reinterpret_cast<float4*>(g_X0 + row * DM + k) = o;
    ln_split_row(o.x, o.y, o.z, o.w, lane, row, lg, lb);
}

// ---------------- per-iter LN ----------------
__global__ __launch_bounds__(256) void ln_kernel(
    const float* __restrict__ lg, const float* __restrict__ lb)
{
    size_t row = (size_t)blockIdx.x * 8 + (threadIdx.x >> 5);
    int lane = threadIdx.x & 31;
    float4 v = *reinterpret_cast<const float4*>(g_XS + row * DM + lane * 4);
    ln_split_row(v.x, v.y, v.z, v.w, lane, row, lg, lb);
}

// ---------------- GEMM: 128M x 64N tile, K=128 one-shot, split-bf16 ----------------
#define TILE_A (128 * KSTRIDE)
#define TILE_B (64 * KSTRIDE)
#define GEMM_SMEM ((2 * TILE_A + 2 * TILE_B) * 2)   // 104448 bytes -> 2 CTAs/SM

template<bool FULL>
__device__ __forceinline__ void gemm_mainloop(
    uint32_t aBaseH, uint32_t aBaseL, uint32_t bBaseH, uint32_t bBaseL,
    float acc[2][4][4])
{
#pragma unroll 2
    for (int k0 = 0; k0 < 128; k0 += 16) {
        uint32_t ah[2][4], al[2][4], bh[4][2], bl[4][2];
#pragma unroll
        for (int mt = 0; mt < 2; mt++) {
            uint32_t off = (uint32_t)(mt * 16 * KSTRIDE + k0) * 2;
            ldm4(ah[mt], aBaseH + off);
            ldm4(al[mt], aBaseL + off);
        }
#pragma unroll
        for (int p = 0; p < 2; p++) {
            uint32_t off = (uint32_t)(p * 16 * KSTRIDE + k0) * 2;
            uint32_t t[4];
            ldm4(t, bBaseH + off);
            bh[2 * p][0] = t[0]; bh[2 * p][1] = t[1];
            bh[2 * p + 1][0] = t[2]; bh[2 * p + 1][1] = t[3];
            if (FULL) {
                ldm4(t, bBaseL + off);
                bl[2 * p][0] = t[0]; bl[2 * p][1] = t[1];
                bl[2 * p + 1][0] = t[2]; bl[2 * p + 1][1] = t[3];
            }
        }
#pragma unroll
        for (int mt = 0; mt < 2; mt++)
#pragma unroll
            for (int nt = 0; nt < 4; nt++) {
                mma_bf16(acc[mt][nt], ah[mt], bh[nt]);
                mma_bf16(acc[mt][nt], al[mt], bh[nt]);
                if (FULL) mma_bf16(acc[mt][nt], ah[mt], bl[nt]);
            }
    }
}

__global__ __launch_bounds__(256) void gemm_kernel()
{
    extern __shared__ __nv_bfloat16 sm[];
    __nv_bfloat16* sAh = sm;
    __nv_bfloat16* sAl = sm + TILE_A;
    __nv_bfloat16* sBh = sm + 2 * TILE_A;
    __nv_bfloat16* sBl = sm + 2 * TILE_A + TILE_B;

    const int tid = threadIdx.x;
    const int mtile = blockIdx.x;
    const int chunk = blockIdx.y;
    const bool full = (chunk >= 8);

    {
        const uint4* gAh = reinterpret_cast<const uint4*>(g_ah + (size_t)mtile * 128 * 128);
        const uint4* gAl = reinterpret_cast<const uint4*>(g_al + (size_t)mtile * 128 * 128);
        for (int i = tid; i < 2048; i += 256) {
            int row = i >> 4, c = i & 15;
            int d = row * KSTRIDE + c * 8;
            *reinterpret_cast<uint4*>(sAh + d) = gAh[i];
            *reinterpret_cast<uint4*>(sAl + d) = gAl[i];
        }
        const uint4* gBh = reinterpret_cast<const uint4*>(g_bh + (size_t)chunk * 64 * 128);
        const uint4* gBl = reinterpret_cast<const uint4*>(g_bl + (size_t)chunk * 64 * 128);
        for (int i = tid; i < 1024; i += 256) {
            int row = i >> 4, c = i & 15;
            int d = row * KSTRIDE + c * 8;
            *reinterpret_cast<uint4*>(sBh + d) = gBh[i];
            if (full) *reinterpret_cast<uint4*>(sBl + d) = gBl[i];
        }
    }
    __syncthreads();

    const int wid = tid >> 5, lane = tid & 31;
    const int wm = wid >> 1, wn = wid & 1;
    const int mBase = wm * 32, nBase = wn * 32;
    const int g = lane >> 3, r = lane & 7;

    const int a_row = r + (g & 1) * 8, a_k = (g >> 1) * 8;
    const int b_n = r + (g >> 1) * 8, b_k = (g & 1) * 8;
    uint32_t aBaseH = smem_u32(sAh) + ((mBase + a_row) * KSTRIDE + a_k) * 2;
    uint32_t aBaseL = smem_u32(sAl) + ((mBase + a_row) * KSTRIDE + a_k) * 2;
    uint32_t bBaseH = smem_u32(sBh) + ((nBase + b_n) * KSTRIDE + b_k) * 2;
    uint32_t bBaseL = smem_u32(sBl) + ((nBase + b_n) * KSTRIDE + b_k) * 2;

    float acc[2][4][4];
#pragma unroll
    for (int mt = 0; mt < 2; mt++)
#pragma unroll
        for (int nt = 0; nt < 4; nt++)
#pragma unroll
            for (int q = 0; q < 4; q++) acc[mt][nt][q] = 0.f;

    if (full) gemm_mainloop<true>(aBaseH, aBaseL, bBaseH, bBaseL, acc);
    else      gemm_mainloop<false>(aBaseH, aBaseL, bBaseH, bBaseL, acc);

    const int qrow = lane >> 2, qcol = (lane & 3) * 2;
#pragma unroll
    for (int mt = 0; mt < 2; mt++) {
#pragma unroll
        for (int nt = 0; nt < 4; nt++) {
            int row0 = mtile * 128 + mBase + mt * 16 + qrow;
            int col = nBase + nt * 8 + qcol;
            int gcol = chunk * 64 + col;
            float b0 = g_bias[gcol], b1 = g_bias[gcol + 1];
            float c0 = acc[mt][nt][0] + b0, c1 = acc[mt][nt][1] + b1;
            float c2 = acc[mt][nt][2] + b0, c3 = acc[mt][nt][3] + b1;
            if (!full) {
                if (row0 < NROWS)
                    *reinterpret_cast<__half2*>(&g_lr[(size_t)row0 * 512 + gcol]) =
                        __halves2half2(__float2half(c0), __float2half(c1));
                if (row0 + 8 < NROWS)
                    *reinterpret_cast<__half2*>(&g_lr[(size_t)(row0 + 8) * 512 + gcol]) =
                        __halves2half2(__float2half(c2), __float2half(c3));
            } else {
                int vc = gcol - 512;
                if (row0 < NROWS) {
                    float2 o; o.x = c0; o.y = c1;
                    *reinterpret_cast<float2*>(&g_v[(size_t)row0 * DM + vc]) = o;
                }
                if (row0 + 8 < NROWS) {
                    float2 o; o.x = c2; o.y = c3;
                    *reinterpret_cast<float2*>(&g_v[(size_t)(row0 + 8) * DM + vc]) = o;
                }
            }
        }
    }
}

// ---------------- scores+softmax: one warp per (frame, head, row) ----------------
// 132192 warps, no smem, no CTA sync: pure throughput shape.
__global__ __launch_bounds__(256) void score_kernel(const float* __restrict__ psw)
{
    const int wtask = blockIdx.x * 8 + (threadIdx.x >> 5);   // grid sized exactly
    const int lane = threadIdx.x & 31;
    const int frame = wtask / 34;
    const int t = wtask - frame * 34;
    const int h = (t >= NJ);
    const int i = t - h * NJ;
    const size_t r0 = (size_t)frame * NJ;
    const int k = lane * 4;

    float4 pw = *reinterpret_cast<const float4*>(psw + k);

    uint2 lu = *reinterpret_cast<const uint2*>(g_lr + (r0 + i) * 512 + h * 128 + k);
    float2 lf0 = __half22float2(*reinterpret_cast<__half2*>(&lu.x));
    float2 lf1 = __half22float2(*reinterpret_cast<__half2*>(&lu.y));

    const int rs = c_row_start[i];
    const int n = c_row_start[i + 1] - rs;    // 2..5, warp-uniform

    float acc[5];
#pragma unroll
    for (int e = 0; e < 5; e++) {
        acc[e] = -1e30f;
        if (e < n) {
            int j = c_nbr[rs + e];
            uint2 ru = *reinterpret_cast<const uint2*>(
                g_lr + (r0 + j) * 512 + 256 + h * 128 + k);
            float2 rf0 = __half22float2(*reinterpret_cast<__half2*>(&ru.x));
            float2 rf1 = __half22float2(*reinterpret_cast<__half2*>(&ru.y));
            float u0 = lf0.x + rf0.x, u1 = lf0.y + rf0.y;
            float u2 = lf1.x + rf1.x, u3 = lf1.y + rf1.y;
            float a = 0.f;
            a = fmaf(fmaxf(u0, 0.2f * u0), pw.x, a);
            a = fmaf(fmaxf(u1, 0.2f * u1), pw.y, a);
            a = fmaf(fmaxf(u2, 0.2f * u2), pw.z, a);
            a = fmaf(fmaxf(u3, 0.2f * u3), pw.w, a);
            acc[e] = a;
        }
    }
    // one interleaved 5-way reduction (convergent: whole warp shares the task).
    // invalid slots reduce garbage (-1e30 sums) but are never used.
#pragma unroll
    for (int o = 16; o; o >>= 1)
#pragma unroll
        for (int e = 0; e < 5; e++)
            acc[e] += __shfl_xor_sync(0xffffffffu, acc[e], o);

    // softmax over n scores, all lanes redundantly
    float m = -1e30f;
#pragma unroll
    for (int e = 0; e < 5; e++) if (e < n) m = fmaxf(m, acc[e]);
    float p[5];
    float s = 0.f;
#pragma unroll
    for (int e = 0; e < 5; e++) {
        p[e] = (e < n) ? __expf(acc[e] - m) : 0.f;
        s += p[e];
    }
    float inv = 1.0f / s;
    if (lane < n) {
        float pv = (lane == 0) ? p[0] : (lane == 1) ? p[1] : (lane == 2) ? p[2]
                 : (lane == 3) ? p[3] : p[4];
        g_sc[(size_t)frame * 98 + h * NEDGE + rs + lane] = pv * inv;
    }
}

// ---------------- attention aggregate: lean, 1 frame / 128-thread CTA ----------------
__global__ __launch_bounds__(128) void attn_kernel(float* __restrict__ dst)
{
    __shared__ __align__(16) float V[NJ * DM];         // 8704 B
    __shared__ __align__(16) float SC[2 * NEDGE];
    __shared__ __align__(16) float SK[NJ];

    const int tid = threadIdx.x;
    const size_t r0 = (size_t)blockIdx.x * NJ;

    {
        const uint4* sv = reinterpret_cast<const uint4*>(g_v + r0 * DM);
        uint4* dv = reinterpret_cast<uint4*>(V);
        for (int i = tid; i < NJ * DM * 4 / 16; i += 128) dv[i] = sv[i];
    }
    if (tid < 2 * NEDGE) SC[tid] = g_sc[(size_t)blockIdx.x * 98 + tid];
    if (tid < NJ) SK[tid] = g_skip[r0 + tid];
    __syncthreads();

    const int h = tid >> 6, d = tid & 63;
    const float* sc = SC + h * NEDGE;
    const float* vf = V + h * 64 + d;
#pragma unroll 1
    for (int j = 0; j < NJ; j++) {
        int rs = c_row_start[j], re = c_row_start[j + 1];
        float acc = 0.f;
        for (int e = rs; e < re; e++)
            acc = fmaf(sc[e], vf[(int)c_nbr[e] * DM], acc);
        float gl = 0.5f * acc * (1.0f + erff(acc * 0.70710678118654752f));
        float sk = SK[j];
        dst[(r0 + j) * DM + tid] = (1.0f - sk) * gl + sk * g_X0[(r0 + j) * DM + tid];
    }
}

// ---------------- launch ----------------
extern "C" void kernel_launch(void* const* d_in, const int* in_sizes, int n_in,
                              void* d_out, int out_size) {
    const float* x   = (const float*)d_in[0];
    const float* og  = (const float*)d_in[1];
    const float* ob  = (const float*)d_in[2];
    const float* lg  = (const float*)d_in[3];
    const float* lb  = (const float*)d_in[4];
    const float* aw  = (const float*)d_in[5];
    const float* ab  = (const float*)d_in[6];
    const float* w1  = (const float*)d_in[7];
    const float* b1  = (const float*)d_in[8];
    const float* w2  = (const float*)d_in[9];
    const float* b2  = (const float*)d_in[10];
    const float* psw = (const float*)d_in[11];
    const float* vw  = (const float*)d_in[13];
    const float* vb  = (const float*)d_in[14];
    float* out = (float*)d_out;

    cudaFuncSetAttribute(gemm_kernel,
                         cudaFuncAttributeMaxDynamicSharedMemorySize, GEMM_SMEM);

    prep_kernel<<<(640 * 128 + 255) / 256, 256>>>(w1, b1, w2, b2, vw, vb, lg, lb, aw, ab);
    outer_fused_kernel<<<NROWS / 8, 256>>>(x, og, ob, lg, lb);

    float* g_xs_ptr = nullptr;
    cudaGetSymbolAddress((void**)&g_xs_ptr, g_XS);

    for (int it = 0; it < 4; it++) {
        gemm_kernel<<<dim3(MTILES, NCHUNK), 256, GEMM_SMEM>>>();
        score_kernel<<<NTASK / 8, 256>>>(psw);
        attn_kernel<<<NFR, 128>>>((it == 3) ? out : g_xs_ptr);
        if (it < 3) ln_kernel<<<NROWS / 8, 256>>>(lg, lb);
    }
}

// round 15
// speedup vs baseline: 1.3948x; 1.0814x over previous
#include <cuda_runtime.h>
#include <cuda_fp16.h>
#include <cuda_bf16.h>
#include <cstdint>

#define NJ 17
#define DM 128
#define NEDGE 49
#define NROWS 66096          // 3888 * 17
#define NFR 3888
#define MTILES 517           // ceil(66096/128)
#define NCHUNK 10            // 640 / 64
#define KST2 72              // smem row stride for K=64 phase (9x16B, odd -> conflict-free)

// ---------------- device scratch ----------------
__device__ float g_XS[(size_t)NROWS * DM];
__device__ float g_X0[(size_t)NROWS * DM];
__device__ float g_skip[NROWS];
__device__ __align__(16) __nv_bfloat16 g_ah[(size_t)MTILES * 128 * 128];
__device__ __align__(16) __nv_bfloat16 g_al[(size_t)MTILES * 128 * 128];
__device__ __align__(16) __nv_bfloat16 g_bh[640 * 128];
__device__ __align__(16) __nv_bfloat16 g_bl[640 * 128];
__device__ float g_bias[640];
__device__ float g_lgaw[DM];
__device__ float g_c1;
__device__ float g_c2;
__device__ __align__(16) __half g_lr[(size_t)NROWS * 512];
__device__ __align__(16) float g_v[(size_t)NROWS * DM];
__device__ float g_sc[(size_t)NFR * 98];

// ---------------- adjacency ----------------
__device__ __constant__ int c_row_start[18] =
    {0,4,7,10,12,15,18,20,23,28,31,33,36,39,41,44,47,49};
__device__ __constant__ signed char c_nbr[NEDGE] = {
    0,1,4,7,  0,1,2,  1,2,3,  2,3,  0,4,5,  4,5,6,  5,6,  0,7,8,
    7,8,9,11,14,  8,9,10,  9,10,  8,11,12,  11,12,13,  12,13,
    8,14,15,  14,15,16,  15,16};

// ---------------- helpers ----------------
__device__ __forceinline__ uint32_t smem_u32(const void* p) {
    uint32_t a;
    asm("{ .reg .u64 t; cvta.to.shared.u64 t, %1; cvt.u32.u64 %0, t; }" : "=r"(a) : "l"(p));
    return a;
}
__device__ __forceinline__ void ldm4(uint32_t* r, uint32_t addr) {
    asm volatile("ldmatrix.sync.aligned.m8n8.x4.shared.b16 {%0,%1,%2,%3}, [%4];"
                 : "=r"(r[0]), "=r"(r[1]), "=r"(r[2]), "=r"(r[3]) : "r"(addr));
}
__device__ __forceinline__ void mma_bf16(float* c, const uint32_t* a, const uint32_t* b) {
    asm volatile("mma.sync.aligned.m16n8k16.row.col.f32.bf16.bf16.f32 "
                 "{%0,%1,%2,%3}, {%4,%5,%6,%7}, {%8,%9}, {%0,%1,%2,%3};"
                 : "+f"(c[0]), "+f"(c[1]), "+f"(c[2]), "+f"(c[3])
                 : "r"(a[0]), "r"(a[1]), "r"(a[2]), "r"(a[3]), "r"(b[0]), "r"(b[1]));
}

// LN + skip + bf16 hi/lo split for one row held by one warp.
__device__ __forceinline__ void ln_split_row(
    float v0, float v1, float v2, float v3, int lane, size_t grow,
    const float* __restrict__ lg, const float* __restrict__ lb)
{
    int k = lane * 4;
    float s = v0 + v1 + v2 + v3;
    float q = v0 * v0 + v1 * v1 + v2 * v2 + v3 * v3;
    float t = v0 * g_lgaw[k] + v1 * g_lgaw[k + 1]
            + v2 * g_lgaw[k + 2] + v3 * g_lgaw[k + 3];
#pragma unroll
    for (int o = 16; o; o >>= 1) {
        s += __shfl_xor_sync(0xffffffffu, s, o);
        q += __shfl_xor_sync(0xffffffffu, q, o);
        t += __shfl_xor_sync(0xffffffffu, t, o);
    }
    float m = s * (1.0f / 128.0f);
    float var = q * (1.0f / 128.0f) - m * m;
    float rstd = rsqrtf(var + 1e-5f);
    if (lane == 0) {
        float ad = rstd * (t - m * g_c1) + g_c2;
        g_skip[grow] = 1.0f / (1.0f + __expf(-ad));
    }
    float n0 = (v0 - m) * rstd * __ldg(lg + k)     + __ldg(lb + k);
    float n1 = (v1 - m) * rstd * __ldg(lg + k + 1) + __ldg(lb + k + 1);
    float n2 = (v2 - m) * rstd * __ldg(lg + k + 2) + __ldg(lb + k + 2);
    float n3 = (v3 - m) * rstd * __ldg(lg + k + 3) + __ldg(lb + k + 3);

    __nv_bfloat16 h0 = __float2bfloat16(n0), h1 = __float2bfloat16(n1);
    __nv_bfloat16 h2 = __float2bfloat16(n2), h3 = __float2bfloat16(n3);
    __nv_bfloat162 ph01 = __halves2bfloat162(h0, h1);
    __nv_bfloat162 ph23 = __halves2bfloat162(h2, h3);
    __nv_bfloat162 pl01 = __halves2bfloat162(
        __float2bfloat16(n0 - __bfloat162float(h0)),
        __float2bfloat16(n1 - __bfloat162float(h1)));
    __nv_bfloat162 pl23 = __halves2bfloat162(
        __float2bfloat16(n2 - __bfloat162float(h2)),
        __float2bfloat16(n3 - __bfloat162float(h3)));
    uint2 uh, ul;
    uh.x = *reinterpret_cast<uint32_t*>(&ph01);
    uh.y = *reinterpret_cast<uint32_t*>(&ph23);
    ul.x = *reinterpret_cast<uint32_t*>(&pl01);
    ul.y = *reinterpret_cast<uint32_t*>(&pl23);
    *reinterpret_cast<uint2*>(g_ah + grow * 128 + k) = uh;
    *reinterpret_cast<uint2*>(g_al + grow * 128 + k) = ul;
}

// ---------------- prologue ----------------
__global__ void prep_kernel(const float* __restrict__ w1, const float* __restrict__ b1,
                            const float* __restrict__ w2, const float* __restrict__ b2,
                            const float* __restrict__ vw, const float* __restrict__ vb,
                            const float* __restrict__ lg, const float* __restrict__ lb,
                            const float* __restrict__ aw, const float* __restrict__ ab)
{
    int idx = blockIdx.x * blockDim.x + threadIdx.x;
    if (idx < 640 * 128) {
        int n = idx >> 7;
        int k = idx & 127;
        float w = (n < 256) ? w1[k * 256 + n]
                : (n < 512) ? w2[k * 256 + (n - 256)]
                            : vw[k * 128 + (n - 512)];
        __nv_bfloat16 h = __float2bfloat16(w);
        __nv_bfloat16 l = __float2bfloat16(w - __bfloat162float(h));
        g_bh[idx] = h;
        g_bl[idx] = l;
    }
    if (idx < 640) {
        g_bias[idx] = (idx < 256) ? b1[idx]
                    : (idx < 512) ? b2[idx - 256]
                                  : vb[idx - 512];
    }
    if (idx < DM) g_lgaw[idx] = lg[idx] * aw[idx];
    if (idx == 0) {
        float c1 = 0.f, c2 = 0.f;
        for (int k = 0; k < DM; k++) { c1 += lg[k] * aw[k]; c2 += lb[k] * aw[k]; }
        g_c1 = c1;
        g_c2 = c2 + ab[0];
    }
}

// ---------------- outer LN + first inner LN/split ----------------
__global__ __launch_bounds__(256) void outer_fused_kernel(
    const float* __restrict__ x,
    const float* __restrict__ og, const float* __restrict__ ob,
    const float* __restrict__ lg, const float* __restrict__ lb)
{
    size_t row = (size_t)blockIdx.x * 8 + (threadIdx.x >> 5);
    int lane = threadIdx.x & 31;
    float4 v = *reinterpret_cast<const float4*>(x + row * DM + lane * 4);
    float s = v.x + v.y + v.z + v.w;
    float q = v.x * v.x + v.y * v.y + v.z * v.z + v.w * v.w;
#pragma unroll
    for (int o = 16; o; o >>= 1) {
        s += __shfl_xor_sync(0xffffffffu, s, o);
        q += __shfl_xor_sync(0xffffffffu, q, o);
    }
    float m = s * (1.0f / 128.0f);
    float rstd = rsqrtf(q * (1.0f / 128.0f) - m * m + 1e-5f);
    int k = lane * 4;
    float4 o;
    o.x = (v.x - m) * rstd * __ldg(og + k)     + __ldg(ob + k);
    o.y = (v.y - m) * rstd * __ldg(og + k + 1) + __ldg(ob + k + 1);
    o.z = (v.z - m) * rstd * __ldg(og + k + 2) + __ldg(ob + k + 2);
    o.w = (v.w - m) * rstd * __ldg(og + k + 3) + __ldg(ob + k + 3);
    *reinterpret_cast<float4*>(g_X0 + row * DM + k) = o;
    ln_split_row(o.x, o.y, o.z, o.w, lane, row, lg, lb);
}

// ---------------- per-iter LN ----------------
__global__ __launch_bounds__(256) void ln_kernel(
    const float* __restrict__ lg, const float* __restrict__ lb)
{
    size_t row = (size_t)blockIdx.x * 8 + (threadIdx.x >> 5);
    int lane = threadIdx.x & 31;
    float4 v = *reinterpret_cast<const float4*>(g_XS + row * DM + lane * 4);
    ln_split_row(v.x, v.y, v.z, v.w, lane, row, lg, lb);
}

// ---------------- GEMM: 128M x 64N tile, K split into 2 phases of 64 ----------------
#define TILE_A2 (128 * KST2)          // elems per A phase buffer (9216)
#define TILE_B2 (64 * KST2)           // elems per B phase buffer (4608)
#define GEMM_SMEM ((2 * TILE_A2 + 2 * TILE_B2) * 2)   // 55296 bytes -> 3 CTAs/SM

__global__ __launch_bounds__(256, 3) void gemm_kernel()
{
    extern __shared__ __nv_bfloat16 sm[];
    __nv_bfloat16* sAh = sm;
    __nv_bfloat16* sAl = sm + TILE_A2;
    __nv_bfloat16* sBh = sm + 2 * TILE_A2;
    __nv_bfloat16* sBl = sm + 2 * TILE_A2 + TILE_B2;

    const int tid = threadIdx.x;
    const int mtile = blockIdx.x;
    const int chunk = blockIdx.y;
    const bool full = (chunk >= 8);

    const uint4* gAh = reinterpret_cast<const uint4*>(g_ah + (size_t)mtile * 128 * 128);
    const uint4* gAl = reinterpret_cast<const uint4*>(g_al + (size_t)mtile * 128 * 128);
    const uint4* gBh = reinterpret_cast<const uint4*>(g_bh + (size_t)chunk * 64 * 128);
    const uint4* gBl = reinterpret_cast<const uint4*>(g_bl + (size_t)chunk * 64 * 128);

    const int wid = tid >> 5, lane = tid & 31;
    const int wm = wid >> 1, wn = wid & 1;
    const int mBase = wm * 32, nBase = wn * 32;
    const int g = lane >> 3, r = lane & 7;
    const int a_row = r + (g & 1) * 8, a_k = (g >> 1) * 8;
    const int b_n = r + (g >> 1) * 8, b_k = (g & 1) * 8;
    const uint32_t aBaseH = smem_u32(sAh) + ((mBase + a_row) * KST2 + a_k) * 2;
    const uint32_t aBaseL = smem_u32(sAl) + ((mBase + a_row) * KST2 + a_k) * 2;
    const uint32_t bBaseH = smem_u32(sBh) + ((nBase + b_n) * KST2 + b_k) * 2;
    const uint32_t bBaseL = smem_u32(sBl) + ((nBase + b_n) * KST2 + b_k) * 2;

    float acc[2][4][4];
#pragma unroll
    for (int mt = 0; mt < 2; mt++)
#pragma unroll
        for (int nt = 0; nt < 4; nt++)
#pragma unroll
            for (int q = 0; q < 4; q++) acc[mt][nt][q] = 0.f;

#pragma unroll 1
    for (int ph = 0; ph < 2; ph++) {
        if (ph) __syncthreads();           // protect smem reuse across phases
        // ---- load this K-phase (64 cols): rows have 16 uint4 in gmem, take 8 ----
        for (int i = tid; i < 1024; i += 256) {
            int row = i >> 3, c = i & 7;
            int gi = row * 16 + ph * 8 + c;
            int d = row * KST2 + c * 8;
            *reinterpret_cast<uint4*>(sAh + d) = gAh[gi];
            *reinterpret_cast<uint4*>(sAl + d) = gAl[gi];
        }
        for (int i = tid; i < 512; i += 256) {
            int row = i >> 3, c = i & 7;
            int gi = row * 16 + ph * 8 + c;
            int d = row * KST2 + c * 8;
            *reinterpret_cast<uint4*>(sBh + d) = gBh[gi];
            if (full) *reinterpret_cast<uint4*>(sBl + d) = gBl[gi];
        }
        __syncthreads();

#pragma unroll
        for (int k0 = 0; k0 < 64; k0 += 16) {
            uint32_t ah[2][4], al[2][4], bh[4][2], bl[4][2];
#pragma unroll
            for (int mt = 0; mt < 2; mt++) {
                uint32_t off = (uint32_t)(mt * 16 * KST2 + k0) * 2;
                ldm4(ah[mt], aBaseH + off);
                ldm4(al[mt], aBaseL + off);
            }
#pragma unroll
            for (int p = 0; p < 2; p++) {
                uint32_t off = (uint32_t)(p * 16 * KST2 + k0) * 2;
                uint32_t t[4];
                ldm4(t, bBaseH + off);
                bh[2 * p][0] = t[0]; bh[2 * p][1] = t[1];
                bh[2 * p + 1][0] = t[2]; bh[2 * p + 1][1] = t[3];
                if (full) {
                    ldm4(t, bBaseL + off);
                    bl[2 * p][0] = t[0]; bl[2 * p][1] = t[1];
                    bl[2 * p + 1][0] = t[2]; bl[2 * p + 1][1] = t[3];
                }
            }
#pragma unroll
            for (int mt = 0; mt < 2; mt++)
#pragma unroll
                for (int nt = 0; nt < 4; nt++) {
                    mma_bf16(acc[mt][nt], ah[mt], bh[nt]);
                    mma_bf16(acc[mt][nt], al[mt], bh[nt]);
                    if (full) mma_bf16(acc[mt][nt], ah[mt], bl[nt]);
                }
        }
    }

    const int qrow = lane >> 2, qcol = (lane & 3) * 2;
#pragma unroll
    for (int mt = 0; mt < 2; mt++) {
#pragma unroll
        for (int nt = 0; nt < 4; nt++) {
            int row0 = mtile * 128 + mBase + mt * 16 + qrow;
            int col = nBase + nt * 8 + qcol;
            int gcol = chunk * 64 + col;
            float b0 = g_bias[gcol], b1 = g_bias[gcol + 1];
            float c0 = acc[mt][nt][0] + b0, c1 = acc[mt][nt][1] + b1;
            float c2 = acc[mt][nt][2] + b0, c3 = acc[mt][nt][3] + b1;
            if (!full) {
                if (row0 < NROWS)
                    *reinterpret_cast<__half2*>(&g_lr[(size_t)row0 * 512 + gcol]) =
                        __halves2half2(__float2half(c0), __float2half(c1));
                if (row0 + 8 < NROWS)
                    *reinterpret_cast<__half2*>(&g_lr[(size_t)(row0 + 8) * 512 + gcol]) =
                        __halves2half2(__float2half(c2), __float2half(c3));
            } else {
                int vc = gcol - 512;
                if (row0 < NROWS) {
                    float2 o; o.x = c0; o.y = c1;
                    *reinterpret_cast<float2*>(&g_v[(size_t)row0 * DM + vc]) = o;
                }
                if (row0 + 8 < NROWS) {
                    float2 o; o.x = c2; o.y = c3;
                    *reinterpret_cast<float2*>(&g_v[(size_t)(row0 + 8) * DM + vc]) = o;
                }
            }
        }
    }
}

// ---------------- scores+softmax: one warp per (frame, row); 16-lane half per head ----------------
__global__ __launch_bounds__(256) void score_kernel(const float* __restrict__ psw)
{
    const int wtask = blockIdx.x * 8 + (threadIdx.x >> 5);   // (frame, row); grid exact
    const int lane = threadIdx.x & 31;
    const int frame = wtask / NJ;
    const int i = wtask - frame * NJ;
    const int half = lane >> 4;          // head
    const int sl = lane & 15;
    const size_t r0 = (size_t)frame * NJ;
    const int kd = sl * 8;               // dim offset within this head (0..120)

    float4 pw0 = __ldg(reinterpret_cast<const float4*>(psw + kd));
    float4 pw1 = __ldg(reinterpret_cast<const float4*>(psw + kd + 4));

    const size_t lhbase = (r0 + i) * 512 + half * 128 + kd;
    uint4 lu = *reinterpret_cast<const uint4*>(g_lr + lhbase);
    float2 la = __half22float2(*reinterpret_cast<__half2*>(&lu.x));
    float2 lb2 = __half22float2(*reinterpret_cast<__half2*>(&lu.y));
    float2 lc = __half22float2(*reinterpret_cast<__half2*>(&lu.z));
    float2 ld = __half22float2(*reinterpret_cast<__half2*>(&lu.w));

    const int rs = c_row_start[i];
    const int n = c_row_start[i + 1] - rs;     // 2..5, warp-uniform

    float acc[5];
#pragma unroll
    for (int e = 0; e < 5; e++) {
        acc[e] = 0.f;
        if (e < n) {
            int j = c_nbr[rs + e];
            uint4 ru = *reinterpret_cast<const uint4*>(
                g_lr + (r0 + j) * 512 + 256 + half * 128 + kd);
            float2 ra = __half22float2(*reinterpret_cast<__half2*>(&ru.x));
            float2 rb = __half22float2(*reinterpret_cast<__half2*>(&ru.y));
            float2 rc = __half22float2(*reinterpret_cast<__half2*>(&ru.z));
            float2 rd = __half22float2(*reinterpret_cast<__half2*>(&ru.w));
            float a = 0.f, u;
            u = la.x + ra.x;  a = fmaf(fmaxf(u, 0.2f * u), pw0.x, a);
            u = la.y + ra.y;  a = fmaf(fmaxf(u, 0.2f * u), pw0.y, a);
            u = lb2.x + rb.x; a = fmaf(fmaxf(u, 0.2f * u), pw0.z, a);
            u = lb2.y + rb.y; a = fmaf(fmaxf(u, 0.2f * u), pw0.w, a);
            u = lc.x + rc.x;  a = fmaf(fmaxf(u, 0.2f * u), pw1.x, a);
            u = lc.y + rc.y;  a = fmaf(fmaxf(u, 0.2f * u), pw1.y, a);
            u = ld.x + rd.x;  a = fmaf(fmaxf(u, 0.2f * u), pw1.z, a);
            u = ld.y + rd.y;  a = fmaf(fmaxf(u, 0.2f * u), pw1.w, a);
            acc[e] = a;
        }
    }
    // reduce within each 16-lane half (offsets < 16 keep bit4 fixed); convergent.
#pragma unroll
    for (int o = 8; o; o >>= 1)
#pragma unroll
        for (int e = 0; e < 5; e++)
            acc[e] += __shfl_xor_sync(0xffffffffu, acc[e], o);

    // softmax over n scores (redundant on all 16 lanes of the half)
    float m = -1e30f;
#pragma unroll
    for (int e = 0; e < 5; e++) if (e < n) m = fmaxf(m, acc[e]);
    float p[5];
    float s = 0.f;
#pragma unroll
    for (int e = 0; e < 5; e++) {
        p[e] = (e < n) ? __expf(acc[e] - m) : 0.f;
        s += p[e];
    }
    float inv = 1.0f / s;
    if (sl < n) {
        float pv = (sl == 0) ? p[0] : (sl == 1) ? p[1] : (sl == 2) ? p[2]
                 : (sl == 3) ? p[3] : p[4];
        g_sc[(size_t)frame * 98 + half * NEDGE + rs + sl] = pv * inv;
    }
}

// ---------------- attention aggregate: lean, 1 frame / 128-thread CTA ----------------
__global__ __launch_bounds__(128) void attn_kernel(float* __restrict__ dst)
{
    __shared__ __align__(16) float V[NJ * DM];
    __shared__ __align__(16) float SC[2 * NEDGE];
    __shared__ __align__(16) float SK[NJ];

    const int tid = threadIdx.x;
    const size_t r0 = (size_t)blockIdx.x * NJ;

    {
        const uint4* sv = reinterpret_cast<const uint4*>(g_v + r0 * DM);
        uint4* dv = reinterpret_cast<uint4*>(V);
        for (int i = tid; i < NJ * DM * 4 / 16; i += 128) dv[i] = sv[i];
    }
    if (tid < 2 * NEDGE) SC[tid] = g_sc[(size_t)blockIdx.x * 98 + tid];
    if (tid < NJ) SK[tid] = g_skip[r0 + tid];
    __syncthreads();

    const int h = tid >> 6, d = tid & 63;
    const float* sc = SC + h * NEDGE;
    const float* vf = V + h * 64 + d;
#pragma unroll 1
    for (int j = 0; j < NJ; j++) {
        int rs = c_row_start[j], re = c_row_start[j + 1];
        float acc = 0.f;
        for (int e = rs; e < re; e++)
            acc = fmaf(sc[e], vf[(int)c_nbr[e] * DM], acc);
        float gl = 0.5f * acc * (1.0f + erff(acc * 0.70710678118654752f));
        float sk = SK[j];
        dst[(r0 + j) * DM + tid] = (1.0f - sk) * gl + sk * g_X0[(r0 + j) * DM + tid];
    }
}

// ---------------- launch ----------------
extern "C" void kernel_launch(void* const* d_in, const int* in_sizes, int n_in,
                              void* d_out, int out_size) {
    const float* x   = (const float*)d_in[0];
    const float* og  = (const float*)d_in[1];
    const float* ob  = (const float*)d_in[2];
    const float* lg  = (const float*)d_in[3];
    const float* lb  = (const float*)d_in[4];
    const float* aw  = (const float*)d_in[5];
    const float* ab  = (const float*)d_in[6];
    const float* w1  = (const float*)d_in[7];
    const float* b1  = (const float*)d_in[8];
    const float* w2  = (const float*)d_in[9];
    const float* b2  = (const float*)d_in[10];
    const float* psw = (const float*)d_in[11];
    const float* vw  = (const float*)d_in[13];
    const float* vb  = (const float*)d_in[14];
    float* out = (float*)d_out;

    cudaFuncSetAttribute(gemm_kernel,
                         cudaFuncAttributeMaxDynamicSharedMemorySize, GEMM_SMEM);

    prep_kernel<<<(640 * 128 + 255) / 256, 256>>>(w1, b1, w2, b2, vw, vb, lg, lb, aw, ab);
    outer_fused_kernel<<<NROWS / 8, 256>>>(x, og, ob, lg, lb);

    float* g_xs_ptr = nullptr;
    cudaGetSymbolAddress((void**)&g_xs_ptr, g_XS);

    for (int it = 0; it < 4; it++) {
        gemm_kernel<<<dim3(MTILES, NCHUNK), 256, GEMM_SMEM>>>();
        score_kernel<<<NROWS / 8, 256>>>(psw);
        attn_kernel<<<NFR, 128>>>((it == 3) ? out : g_xs_ptr);
        if (it < 3) ln_kernel<<<NROWS / 8, 256>>>(lg, lb);
    }
}